// round 1
// baseline (speedup 1.0000x reference)
#include <cuda_runtime.h>
#include <cuda_bf16.h>

#define NQ 8
// Upper-triangle flat index for 8x8: valid for compile-time-constant i<=j.
#define MU(i, j) Mu[(i) * NQ + (j) - ((i) * ((i) + 1)) / 2]

__global__ void __launch_bounds__(256) acrobot_dyn_kernel(
    const float* __restrict__ q_in, const float* __restrict__ v_in,
    const float* __restrict__ u_in, const float* __restrict__ p,
    float* __restrict__ out, int B)
{
    int b = blockIdx.x * blockDim.x + threadIdx.x;
    if (b >= B) return;

    // ---- params (broadcast; L1/L2 resident) ----
    float ms[NQ], ls[NQ], taus[NQ];
#pragma unroll
    for (int i = 0; i < NQ; i++) {
        ms[i]   = __ldg(p + i);
        ls[i]   = __ldg(p + NQ + i);
        taus[i] = __ldg(p + 2 * NQ + 1 + i);
    }
    const float g = __ldg(p + 2 * NQ);

    // suffix sums of ms and Is = ms*ls^2/12
    float ms_suf[NQ], Is_suf[NQ];
    {
        float a = 0.0f, c = 0.0f;
#pragma unroll
        for (int i = NQ - 1; i >= 0; i--) {
            a += ms[i];
            c += ms[i] * ls[i] * ls[i] * (1.0f / 12.0f);
            ms_suf[i] = a;
            Is_suf[i] = c;
        }
    }

    // ---- per-sample inputs (vectorized, coalesced) ----
    const float4 qa = *(const float4*)(q_in + (size_t)b * NQ);
    const float4 qb = *(const float4*)(q_in + (size_t)b * NQ + 4);
    const float4 va = *(const float4*)(v_in + (size_t)b * NQ);
    const float4 vb = *(const float4*)(v_in + (size_t)b * NQ + 4);
    const float4 ua = *(const float4*)(u_in + (size_t)b * NQ);
    const float4 ub = *(const float4*)(u_in + (size_t)b * NQ + 4);
    const float qq[NQ] = {qa.x, qa.y, qa.z, qa.w, qb.x, qb.y, qb.z, qb.w};
    const float vv[NQ] = {va.x, va.y, va.z, va.w, vb.x, vb.y, vb.z, vb.w};
    const float uu[NQ] = {ua.x, ua.y, ua.z, ua.w, ub.x, ub.y, ub.z, ub.w};

    // cumsums and sincos
    float cs[NQ], cv[NQ], sn[NQ], cn[NQ];
    {
        float aq = 0.0f, av = 0.0f;
#pragma unroll
        for (int i = 0; i < NQ; i++) {
            aq += qq[i];
            av += vv[i];
            cs[i] = aq;
            cv[i] = av;
            sincosf(aq, &sn[i], &cn[i]);
        }
    }

    // ---- mass matrix (upper triangle) + Coriolis contractions ----
    float Mu[(NQ * (NQ + 1)) / 2];
    float r1[NQ], r2[NQ];
#pragma unroll
    for (int i = 0; i < NQ; i++) { r1[i] = 0.0f; r2[i] = 0.0f; }

#pragma unroll
    for (int i = 0; i < NQ; i++) {
        MU(i, i) = ls[i] * ls[i] * (ms_suf[i] - 0.75f * ms[i]) + Is_suf[i];
#pragma unroll
        for (int j = i + 1; j < NQ; j++) {
            const float A  = ls[i] * ls[j] * (ms_suf[j] - 0.5f * ms[j]);
            const float cd = cn[i] * cn[j] + sn[i] * sn[j];  // cos(cs_i - cs_j)
            const float sd = sn[i] * cn[j] - cn[i] * sn[j];  // sin(cs_i - cs_j)
            MU(i, j) = A * cd + Is_suf[j];
            const float T = A * sd;  // T[i][j]; T[j][i] = -T
            r1[i] += T * vv[j];
            r1[j] -= T * vv[i];
            r2[i] += T * vv[j] * cv[j];
            r2[j] -= T * vv[i] * cv[i];
        }
    }

    // ---- rhs = taus*u - Cv - G (suffix sums fused) ----
    float x[NQ];
    {
        float suffR = 0.0f, suffG = 0.0f;
#pragma unroll
        for (int k = NQ - 1; k >= 0; k--) {
            suffR += vv[k] * r1[k];
            suffG += ls[k] * (ms_suf[k] - 0.5f * ms[k]) * sn[k];
            const float Cv = -cv[k] * r1[k] + r2[k] + suffR;
            const float G  = g * suffG;
            x[k] = taus[k] * uu[k] - Cv - G;
        }
    }

    // ---- solve M x = rhs; symmetric Gaussian elimination, fully unrolled ----
#pragma unroll
    for (int k = 0; k < NQ; k++) {
        const float inv = 1.0f / MU(k, k);
#pragma unroll
        for (int i = k + 1; i < NQ; i++) {
            const float f = MU(k, i) * inv;  // == M[i][k]/M[k][k] (symmetry preserved)
#pragma unroll
            for (int j = i; j < NQ; j++) MU(i, j) -= f * MU(k, j);
            x[i] -= f * x[k];
        }
    }
#pragma unroll
    for (int k = NQ - 1; k >= 0; k--) {
        float s = x[k];
#pragma unroll
        for (int j = k + 1; j < NQ; j++) s -= MU(k, j) * x[j];
        x[k] = s / MU(k, k);
    }

    // ---- store ----
    float4 o0 = make_float4(x[0], x[1], x[2], x[3]);
    float4 o1 = make_float4(x[4], x[5], x[6], x[7]);
    *(float4*)(out + (size_t)b * NQ)     = o0;
    *(float4*)(out + (size_t)b * NQ + 4) = o1;
}

extern "C" void kernel_launch(void* const* d_in, const int* in_sizes, int n_in,
                              void* d_out, int out_size) {
    const float* q = (const float*)d_in[0];
    const float* v = (const float*)d_in[1];
    const float* u = (const float*)d_in[2];
    const float* p = (const float*)d_in[3];
    float* out = (float*)d_out;
    const int B = in_sizes[0] / NQ;
    const int threads = 256;
    const int blocks = (B + threads - 1) / threads;
    acrobot_dyn_kernel<<<blocks, threads>>>(q, v, u, p, out, B);
}

// round 2
// speedup vs baseline: 1.0805x; 1.0805x over previous
#include <cuda_runtime.h>
#include <cuda_bf16.h>

#define NQ 8
// Upper-triangle flat index for 8x8: valid for compile-time-constant i<=j.
#define MU(i, j) Mu[(i) * NQ + (j) - ((i) * ((i) + 1)) / 2]

__global__ void __launch_bounds__(256) acrobot_dyn_kernel(
    const float* __restrict__ q_in, const float* __restrict__ v_in,
    const float* __restrict__ u_in, const float* __restrict__ p,
    float* __restrict__ out, int B)
{
    int b = blockIdx.x * blockDim.x + threadIdx.x;
    if (b >= B) return;

    // ---- per-sample inputs first (get memory in flight early) ----
    const float4 qa = *(const float4*)(q_in + (size_t)b * NQ);
    const float4 qb = *(const float4*)(q_in + (size_t)b * NQ + 4);
    const float4 va = *(const float4*)(v_in + (size_t)b * NQ);
    const float4 vb = *(const float4*)(v_in + (size_t)b * NQ + 4);
    const float4 ua = *(const float4*)(u_in + (size_t)b * NQ);
    const float4 ub = *(const float4*)(u_in + (size_t)b * NQ + 4);

    // ---- params (broadcast; L1/L2 resident) ----
    float ms[NQ], ls[NQ], taus[NQ];
#pragma unroll
    for (int i = 0; i < NQ; i++) {
        ms[i]   = __ldg(p + i);
        ls[i]   = __ldg(p + NQ + i);
        taus[i] = __ldg(p + 2 * NQ + 1 + i);
    }
    const float g = __ldg(p + 2 * NQ);

    // suffix sums of ms and Is = ms*ls^2/12
    float ms_suf[NQ], Is_suf[NQ];
    {
        float a = 0.0f, c = 0.0f;
#pragma unroll
        for (int i = NQ - 1; i >= 0; i--) {
            a += ms[i];
            c += ms[i] * ls[i] * ls[i] * (1.0f / 12.0f);
            ms_suf[i] = a;
            Is_suf[i] = c;
        }
    }

    const float qq[NQ] = {qa.x, qa.y, qa.z, qa.w, qb.x, qb.y, qb.z, qb.w};
    const float vv[NQ] = {va.x, va.y, va.z, va.w, vb.x, vb.y, vb.z, vb.w};
    const float uu[NQ] = {ua.x, ua.y, ua.z, ua.w, ub.x, ub.y, ub.z, ub.w};

    // cumsums and fast sincos (RRO + MUFU)
    float cv[NQ], sn[NQ], cn[NQ], vcv[NQ];
    {
        float aq = 0.0f, av = 0.0f;
#pragma unroll
        for (int i = 0; i < NQ; i++) {
            aq += qq[i];
            av += vv[i];
            cv[i] = av;
            __sincosf(aq, &sn[i], &cn[i]);
            vcv[i] = vv[i] * av;
        }
    }

    // ---- mass matrix (upper triangle) + Coriolis contractions ----
    float Mu[(NQ * (NQ + 1)) / 2];
    float r1[NQ], r2[NQ];
#pragma unroll
    for (int i = 0; i < NQ; i++) { r1[i] = 0.0f; r2[i] = 0.0f; }

#pragma unroll
    for (int i = 0; i < NQ; i++) {
        MU(i, i) = ls[i] * ls[i] * (ms_suf[i] - 0.75f * ms[i]) + Is_suf[i];
#pragma unroll
        for (int j = i + 1; j < NQ; j++) {
            const float A  = ls[i] * ls[j] * (ms_suf[j] - 0.5f * ms[j]);
            const float cd = cn[i] * cn[j] + sn[i] * sn[j];  // cos(cs_i - cs_j)
            const float sd = sn[i] * cn[j] - cn[i] * sn[j];  // sin(cs_i - cs_j)
            MU(i, j) = A * cd + Is_suf[j];
            const float T = A * sd;  // T[i][j]; T[j][i] = -T
            r1[i] += T * vv[j];
            r1[j] -= T * vv[i];
            r2[i] += T * vcv[j];
            r2[j] -= T * vcv[i];
        }
    }

    // ---- rhs = taus*u - Cv - G (suffix sums fused) ----
    float x[NQ];
    {
        float suffR = 0.0f, suffG = 0.0f;
#pragma unroll
        for (int k = NQ - 1; k >= 0; k--) {
            suffR += vv[k] * r1[k];
            suffG += ls[k] * (ms_suf[k] - 0.5f * ms[k]) * sn[k];
            const float Cv = -cv[k] * r1[k] + r2[k] + suffR;
            const float G  = g * suffG;
            x[k] = taus[k] * uu[k] - Cv - G;
        }
    }

    // ---- solve M x = rhs; symmetric Gaussian elimination, fully unrolled ----
#pragma unroll
    for (int k = 0; k < NQ; k++) {
        const float inv = __fdividef(1.0f, MU(k, k));
#pragma unroll
        for (int i = k + 1; i < NQ; i++) {
            const float f = MU(k, i) * inv;  // == M[i][k]/M[k][k] (symmetry preserved)
#pragma unroll
            for (int j = i; j < NQ; j++) MU(i, j) -= f * MU(k, j);
            x[i] -= f * x[k];
        }
    }
#pragma unroll
    for (int k = NQ - 1; k >= 0; k--) {
        float s = x[k];
#pragma unroll
        for (int j = k + 1; j < NQ; j++) s -= MU(k, j) * x[j];
        x[k] = s * __fdividef(1.0f, MU(k, k));
    }

    // ---- store ----
    float4 o0 = make_float4(x[0], x[1], x[2], x[3]);
    float4 o1 = make_float4(x[4], x[5], x[6], x[7]);
    *(float4*)(out + (size_t)b * NQ)     = o0;
    *(float4*)(out + (size_t)b * NQ + 4) = o1;
}

extern "C" void kernel_launch(void* const* d_in, const int* in_sizes, int n_in,
                              void* d_out, int out_size) {
    const float* q = (const float*)d_in[0];
    const float* v = (const float*)d_in[1];
    const float* u = (const float*)d_in[2];
    const float* p = (const float*)d_in[3];
    float* out = (float*)d_out;
    const int B = in_sizes[0] / NQ;
    const int threads = 256;
    const int blocks = (B + threads - 1) / threads;
    acrobot_dyn_kernel<<<blocks, threads>>>(q, v, u, p, out, B);
}

// round 3
// speedup vs baseline: 1.2727x; 1.1779x over previous
#include <cuda_runtime.h>
#include <cuda_bf16.h>

#define NQ 8
// Upper-triangle flat index for 8x8 (compile-time i<=j).
#define MU(i, j) Mu[(i) * NQ + (j) - ((i) * ((i) + 1)) / 2]
// Pair index for i<j among the 28 (i<j) pairs, row-major.
#define PIDX(i, j) (7 * (i) - ((i) * ((i) - 1)) / 2 + ((j) - (i) - 1))

__global__ void __launch_bounds__(128, 6) acrobot_dyn_kernel(
    const float* __restrict__ q_in, const float* __restrict__ v_in,
    const float* __restrict__ u_in, const float* __restrict__ p,
    float* __restrict__ out, int B)
{
    // ---- uniform param-derived coefficients, computed once per CTA ----
    __shared__ float sA[28];   // ls_i*ls_j*(ms_suf_j - 0.5*ms_j) for i<j
    __shared__ float sD[NQ];   // diagonal of M
    __shared__ float sIs[NQ];  // Is suffix sums (off-diag additive term)
    __shared__ float sGc[NQ];  // g * ls_j * (ms_suf_j - 0.5*ms_j)
    __shared__ float sTau[NQ];

    if (threadIdx.x == 0) {
        float ms[NQ], ls[NQ], ms_suf[NQ], Is_suf[NQ];
#pragma unroll
        for (int i = 0; i < NQ; i++) {
            ms[i] = p[i];
            ls[i] = p[NQ + i];
            sTau[i] = p[2 * NQ + 1 + i];
        }
        const float g = p[2 * NQ];
        float a = 0.0f, c = 0.0f;
#pragma unroll
        for (int i = NQ - 1; i >= 0; i--) {
            a += ms[i];
            c += ms[i] * ls[i] * ls[i] * (1.0f / 12.0f);
            ms_suf[i] = a;
            Is_suf[i] = c;
        }
#pragma unroll
        for (int i = 0; i < NQ; i++) {
            sD[i]  = ls[i] * ls[i] * (ms_suf[i] - 0.75f * ms[i]) + Is_suf[i];
            sIs[i] = Is_suf[i];
            sGc[i] = g * ls[i] * (ms_suf[i] - 0.5f * ms[i]);
#pragma unroll
            for (int j = i + 1; j < NQ; j++)
                sA[PIDX(i, j)] = ls[i] * ls[j] * (ms_suf[j] - 0.5f * ms[j]);
        }
    }
    __syncthreads();

    const int b = blockIdx.x * blockDim.x + threadIdx.x;
    if (b >= B) return;

    // ---- per-sample q, v (coalesced float4) ----
    const float4 qa = *(const float4*)(q_in + (size_t)b * NQ);
    const float4 qb = *(const float4*)(q_in + (size_t)b * NQ + 4);
    const float4 va = *(const float4*)(v_in + (size_t)b * NQ);
    const float4 vb = *(const float4*)(v_in + (size_t)b * NQ + 4);
    const float qq[NQ] = {qa.x, qa.y, qa.z, qa.w, qb.x, qb.y, qb.z, qb.w};
    const float vv[NQ] = {va.x, va.y, va.z, va.w, vb.x, vb.y, vb.z, vb.w};

    // cumsums + fast sincos
    float cv[NQ], sn[NQ], cn[NQ], vcv[NQ];
    {
        float aq = 0.0f, av = 0.0f;
#pragma unroll
        for (int i = 0; i < NQ; i++) {
            aq += qq[i];
            av += vv[i];
            cv[i] = av;
            __sincosf(aq, &sn[i], &cn[i]);
            vcv[i] = vv[i] * av;
        }
    }

    // ---- mass matrix (upper triangle) + Coriolis contractions ----
    float Mu[(NQ * (NQ + 1)) / 2];
    float r1[NQ], r2[NQ];
#pragma unroll
    for (int i = 0; i < NQ; i++) { r1[i] = 0.0f; r2[i] = 0.0f; }

#pragma unroll
    for (int i = 0; i < NQ; i++) {
        MU(i, i) = sD[i];
#pragma unroll
        for (int j = i + 1; j < NQ; j++) {
            const float A  = sA[PIDX(i, j)];
            const float cd = cn[i] * cn[j] + sn[i] * sn[j];  // cos(cs_i - cs_j)
            const float sd = sn[i] * cn[j] - cn[i] * sn[j];  // sin(cs_i - cs_j)
            MU(i, j) = A * cd + sIs[j];
            const float T = A * sd;  // T[i][j]; T[j][i] = -T
            r1[i] += T * vv[j];
            r1[j] -= T * vv[i];
            r2[i] += T * vcv[j];
            r2[j] -= T * vcv[i];
        }
    }

    // ---- rhs = taus*u - Cv - G (u loaded late to cut liveness) ----
    const float4 ua = *(const float4*)(u_in + (size_t)b * NQ);
    const float4 ub = *(const float4*)(u_in + (size_t)b * NQ + 4);
    const float uu[NQ] = {ua.x, ua.y, ua.z, ua.w, ub.x, ub.y, ub.z, ub.w};

    float x[NQ];
    {
        float suffR = 0.0f, suffG = 0.0f;
#pragma unroll
        for (int k = NQ - 1; k >= 0; k--) {
            suffR += vv[k] * r1[k];
            suffG += sGc[k] * sn[k];
            const float Cv = -cv[k] * r1[k] + r2[k] + suffR;
            x[k] = sTau[k] * uu[k] - Cv - suffG;
        }
    }

    // ---- solve M x = rhs; symmetric Gaussian elimination, unrolled ----
    float invd[NQ];
#pragma unroll
    for (int k = 0; k < NQ; k++) {
        const float inv = __fdividef(1.0f, MU(k, k));
        invd[k] = inv;
#pragma unroll
        for (int i = k + 1; i < NQ; i++) {
            const float f = MU(k, i) * inv;  // == M[i][k]/M[k][k] (symmetry)
#pragma unroll
            for (int j = i; j < NQ; j++) MU(i, j) -= f * MU(k, j);
            x[i] -= f * x[k];
        }
    }
#pragma unroll
    for (int k = NQ - 1; k >= 0; k--) {
        float s = x[k];
#pragma unroll
        for (int j = k + 1; j < NQ; j++) s -= MU(k, j) * x[j];
        x[k] = s * invd[k];
    }

    // ---- store ----
    *(float4*)(out + (size_t)b * NQ)     = make_float4(x[0], x[1], x[2], x[3]);
    *(float4*)(out + (size_t)b * NQ + 4) = make_float4(x[4], x[5], x[6], x[7]);
}

extern "C" void kernel_launch(void* const* d_in, const int* in_sizes, int n_in,
                              void* d_out, int out_size) {
    const float* q = (const float*)d_in[0];
    const float* v = (const float*)d_in[1];
    const float* u = (const float*)d_in[2];
    const float* p = (const float*)d_in[3];
    float* out = (float*)d_out;
    const int B = in_sizes[0] / NQ;
    const int threads = 128;
    const int blocks = (B + threads - 1) / threads;
    acrobot_dyn_kernel<<<blocks, threads>>>(q, v, u, p, out, B);
}